// round 10
// baseline (speedup 1.0000x reference)
#include <cuda_runtime.h>
#include <cuda_fp16.h>

#define D 128
#define H 64
#define NMAX 100032
#define EMAX 1600000
#define FULL 0xffffffffu
#define CAP 160

typedef unsigned long long ull;

// ---------------- packed f32x2 helpers -----------------------------------------
__device__ __forceinline__ ull pk2(float lo, float hi) {
    ull r;
    asm("mov.b64 %0, {%1, %2};" : "=l"(r) : "f"(lo), "f"(hi));
    return r;
}
__device__ __forceinline__ void upk2(float& lo, float& hi, ull v) {
    asm("mov.b64 {%0, %1}, %2;" : "=f"(lo), "=f"(hi) : "l"(v));
}
__device__ __forceinline__ ull ffma2(ull a, ull b, ull c) {
    ull d;
    asm("fma.rn.f32x2 %0, %1, %2, %3;" : "=l"(d) : "l"(a), "l"(b), "l"(c));
    return d;
}
__device__ __forceinline__ float hsum2(ull v) {
    float lo, hi; upk2(lo, hi, v); return lo + hi;
}

// ---------------- scratch (static device globals; no allocations) -------------
__device__ float g_weights[NMAX];
__device__ int   g_deg[NMAX];
__device__ int   g_rowoff[NMAX + 1];
__device__ int   g_cursor[NMAX];
__device__ int   g_csrcol[EMAX];
__device__ int   g_partials[256];
__device__ int   g_is64;
__device__ uint2 g_xh[(size_t)NMAX * 32];   // x as fp16, same layout (4 halves per lane slot)

// ---------------- fp16 conversion ----------------------------------------------
__global__ void k_tohalf(const float4* __restrict__ x4, int total4) {
    int i = blockIdx.x * blockDim.x + threadIdx.x;
    if (i < total4) {
        float4 v = x4[i];
        __half2 a = __floats2half2_rn(v.x, v.y);
        __half2 b = __floats2half2_rn(v.z, v.w);
        uint2 r;
        r.x = *(unsigned*)&a;
        r.y = *(unsigned*)&b;
        g_xh[i] = r;
    }
}

// ---------------- dtype detection (1 warp) -------------------------------------
__global__ void k_detect(const void* __restrict__ ei, int E, int N) {
    const long long* e64 = (const long long*)ei;
    int lane = threadIdx.x;
    int ok = 1;
    if (lane < E) {
        long long v = e64[lane];
        ok = (v >= 0 && v < (long long)N) ? 1 : 0;
    }
    unsigned m = __ballot_sync(FULL, ok);
    if (lane == 0) g_is64 = (m == FULL) ? 1 : 0;
}

__device__ __forceinline__ int edge_at(const void* ei, size_t idx, int is64, int N) {
    long long v = is64 ? ((const long long*)ei)[idx] : (long long)((const int*)ei)[idx];
    if (v < 0) v = 0;
    if (v >= N) v = N - 1;
    return (int)v;
}

__global__ void k_zero(int N) {
    int i = blockIdx.x * blockDim.x + threadIdx.x;
    if (i < N) g_deg[i] = 0;
}

// ---------------- gate (f32x2 + shuffles) --------------------------------------
__global__ void k_gate(const float4* __restrict__ x4, const float* __restrict__ Wsim,
                       const float* __restrict__ bsim, const float* __restrict__ wvec,
                       const float* __restrict__ bvec, int N) {
    __shared__ float4 sWp[64 * 32];
    __shared__ float sb[H], sv[H];
    int tid = threadIdx.x;
    for (int i = tid; i < 64 * 32; i += blockDim.x) {
        int kp = i >> 5, l = i & 31;
        sWp[i] = make_float4(Wsim[(2 * kp) * H + 2 * l], Wsim[(2 * kp + 1) * H + 2 * l],
                             Wsim[(2 * kp) * H + 2 * l + 1], Wsim[(2 * kp + 1) * H + 2 * l + 1]);
    }
    if (tid < H) { sb[tid] = bsim[tid]; sv[tid] = wvec[tid]; }
    __syncthreads();
    float bv = bvec[0];
    const ulonglong2* Wv = (const ulonglong2*)sWp;

    int lane = tid & 31, wp = tid >> 5;
    int gw = blockIdx.x * (blockDim.x >> 5) + wp;
    int nw = gridDim.x * (blockDim.x >> 5);
    int ngroups = (N + 3) >> 2;
    for (int g = gw; g < ngroups; g += nw) {
        int n0 = g * 4;
        ull A[4], B[4], a0[4], a1[4];
        #pragma unroll
        for (int t = 0; t < 4; t++) {
            int n = n0 + t;
            float4 xv = (n < N) ? x4[(size_t)n * 32 + lane] : make_float4(0.f, 0.f, 0.f, 0.f);
            A[t] = pk2(xv.x, xv.y);
            B[t] = pk2(xv.z, xv.w);
            a0[t] = pk2(sb[2 * lane], 0.f);
            a1[t] = pk2(sb[2 * lane + 1], 0.f);
        }
        #pragma unroll 4
        for (int kk = 0; kk < 32; kk++) {
            ulonglong2 w0 = Wv[(2 * kk) * 32 + lane];
            ulonglong2 w1 = Wv[(2 * kk + 1) * 32 + lane];
            #pragma unroll
            for (int t = 0; t < 4; t++) {
                ull pa = __shfl_sync(FULL, A[t], kk);
                ull pb = __shfl_sync(FULL, B[t], kk);
                a0[t] = ffma2(pa, w0.x, a0[t]);
                a0[t] = ffma2(pb, w1.x, a0[t]);
                a1[t] = ffma2(pa, w0.y, a1[t]);
                a1[t] = ffma2(pb, w1.y, a1[t]);
            }
        }
        #pragma unroll
        for (int t = 0; t < 4; t++) {
            float h0 = tanhf(hsum2(a0[t]));
            float h1 = tanhf(hsum2(a1[t]));
            float s = h0 * sv[2 * lane] + h1 * sv[2 * lane + 1];
            #pragma unroll
            for (int o = 16; o > 0; o >>= 1) s += __shfl_xor_sync(FULL, s, o);
            if (lane == 0 && n0 + t < N)
                g_weights[n0 + t] = 1.f / (1.f + __expf(-(s + bv)));
        }
    }
}

// ---------------- CSR build ----------------------------------------------------
__global__ void k_hist(const void* __restrict__ ei, int E, int N) {
    int is64 = g_is64;
    int i = blockIdx.x * blockDim.x + threadIdx.x;
    int stride = gridDim.x * blockDim.x;
    for (; i < E; i += stride) atomicAdd(&g_deg[edge_at(ei, i, is64, N)], 1);
}

__global__ void k_scan1(int N) {
    int i = blockIdx.x * 1024 + threadIdx.x;
    int v = (i < N) ? g_deg[i] : 0;
    #pragma unroll
    for (int o = 16; o > 0; o >>= 1) v += __shfl_xor_sync(FULL, v, o);
    __shared__ int ws[32];
    int lane = threadIdx.x & 31, w = threadIdx.x >> 5;
    if (lane == 0) ws[w] = v;
    __syncthreads();
    if (w == 0) {
        int s = ws[lane];
        #pragma unroll
        for (int o = 16; o > 0; o >>= 1) s += __shfl_xor_sync(FULL, s, o);
        if (lane == 0) g_partials[blockIdx.x] = s;
    }
}

__global__ void k_scan2(int nblk, int N, int E) {
    __shared__ int s[128];
    int tid = threadIdx.x;
    int v = (tid < nblk) ? g_partials[tid] : 0;
    s[tid] = v;
    __syncthreads();
    for (int o = 1; o < 128; o <<= 1) {
        int t = 0;
        if (tid >= o) t = s[tid - o];
        __syncthreads();
        s[tid] += t;
        __syncthreads();
    }
    if (tid < nblk) g_partials[tid] = s[tid] - v;
    if (tid == 0) g_rowoff[N] = E;
}

__global__ void k_scan3(int N) {
    int i = blockIdx.x * 1024 + threadIdx.x;
    int lane = threadIdx.x & 31, w = threadIdx.x >> 5;
    int v = (i < N) ? g_deg[i] : 0;
    int s = v;
    #pragma unroll
    for (int o = 1; o < 32; o <<= 1) {
        int t = __shfl_up_sync(FULL, s, o);
        if (lane >= o) s += t;
    }
    __shared__ int ws[32];
    if (lane == 31) ws[w] = s;
    __syncthreads();
    if (w == 0) {
        int t2 = ws[lane];
        #pragma unroll
        for (int o = 1; o < 32; o <<= 1) {
            int u = __shfl_up_sync(FULL, t2, o);
            if (lane >= o) t2 += u;
        }
        ws[lane] = t2;
    }
    __syncthreads();
    int excl = s - v + ((w > 0) ? ws[w - 1] : 0) + g_partials[blockIdx.x];
    if (i < N) { g_rowoff[i] = excl; g_cursor[i] = excl; }
}

__global__ void k_fill(const void* __restrict__ ei, int E, int N) {
    int is64 = g_is64;
    int i = blockIdx.x * blockDim.x + threadIdx.x;
    int stride = gridDim.x * blockDim.x;
    for (; i < E; i += stride) {
        int r = edge_at(ei, i, is64, N);
        int c = edge_at(ei, (size_t)E + i, is64, N);
        int pos = atomicAdd(&g_cursor[r], 1);
        if (pos >= 0 && pos < EMAX) g_csrcol[pos] = c;
    }
}

// ---------------- FUSED: fp16 staged gather + MLP1 + MLP2 + residual -----------
__global__ void k_fused(const float4* __restrict__ x4,
                        const float* __restrict__ W1, const float* __restrict__ b1,
                        const float* __restrict__ W2, const float* __restrict__ b2,
                        float4* __restrict__ out4, int N) {
    extern __shared__ float sm[];
    float4* sW1p = (float4*)sm;
    float2* sW2p = (float2*)(sm + 8192);
    float*  sb1  = sm + 16384;
    float4* sb2  = (float4*)(sm + 16448);

    int tid = threadIdx.x;
    for (int i = tid; i < 64 * 32; i += blockDim.x) {
        int kp = i >> 5, l = i & 31;
        sW1p[i] = make_float4(W1[(2 * kp) * H + 2 * l], W1[(2 * kp + 1) * H + 2 * l],
                              W1[(2 * kp) * H + 2 * l + 1], W1[(2 * kp + 1) * H + 2 * l + 1]);
    }
    for (int i = tid; i < 32 * D; i += blockDim.x) {
        int m = i >> 7, d = i & 127;
        sW2p[i] = make_float2(W2[(2 * m) * D + d], W2[(2 * m + 1) * D + d]);
    }
    if (tid < H) sb1[tid] = b1[tid];
    if (tid < 32) sb2[tid] = ((const float4*)b2)[tid];
    __syncthreads();

    const ulonglong2* W1v = (const ulonglong2*)sW1p;
    const ulonglong2* W2v = (const ulonglong2*)sW2p;

    int lane = tid & 31, wp = tid >> 5;
    int*   scol = (int*)(sm + 16576) + wp * 2 * CAP;
    float* swt  = (float*)(scol + CAP);

    int gw = blockIdx.x * (blockDim.x >> 5) + wp;
    int nw = gridDim.x * (blockDim.x >> 5);
    int ngroups = (N + 3) >> 2;

    for (int g = gw; g < ngroups; g += nw) {
        int n0 = g * 4;
        int nlast = (n0 + 4 < N) ? n0 + 4 : N;

        // ---- cooperative stage of this group's contiguous CSR slab
        int S = g_rowoff[n0];
        int Eend = g_rowoff[nlast];
        int degT = Eend - S;
        int nst = (degT < CAP) ? degT : CAP;
        __syncwarp();
        for (int i = lane; i < nst; i += 32) {
            int c = g_csrcol[S + i];
            scol[i] = c;
            swt[i] = g_weights[c];
        }
        __syncwarp();

        // ---- gather from fp16 x (256B/edge from L2), fp32 accumulate
        float4 acc[4];
        #pragma unroll
        for (int t = 0; t < 4; t++) {
            acc[t] = make_float4(0.f, 0.f, 0.f, 0.f);
            int n = n0 + t;
            if (n >= N) continue;
            int s = g_rowoff[n] - S;
            int e = g_rowoff[n + 1] - S;
            int elim = (e < nst) ? e : nst;
            int p = s;
            for (; p + 8 <= elim; p += 8) {
                int   c[8]; float wv[8]; uint2 hv[8];
                #pragma unroll
                for (int q = 0; q < 8; q++) c[q] = scol[p + q];
                #pragma unroll
                for (int q = 0; q < 8; q++) wv[q] = swt[p + q];
                #pragma unroll
                for (int q = 0; q < 8; q++) hv[q] = g_xh[(size_t)c[q] * 32 + lane];
                #pragma unroll
                for (int q = 0; q < 8; q++) {
                    float2 f01 = __half22float2(*(__half2*)&hv[q].x);
                    float2 f23 = __half22float2(*(__half2*)&hv[q].y);
                    acc[t].x += f01.x * wv[q];
                    acc[t].y += f01.y * wv[q];
                    acc[t].z += f23.x * wv[q];
                    acc[t].w += f23.y * wv[q];
                }
            }
            for (; p < elim; p++) {
                int cc = scol[p];
                float w = swt[p];
                uint2 hr = g_xh[(size_t)cc * 32 + lane];
                float2 f01 = __half22float2(*(__half2*)&hr.x);
                float2 f23 = __half22float2(*(__half2*)&hr.y);
                acc[t].x += f01.x * w; acc[t].y += f01.y * w;
                acc[t].z += f23.x * w; acc[t].w += f23.y * w;
            }
            // overflow beyond staged CAP (essentially never for Poisson(64))
            for (int p2 = (s > nst ? s : nst); p2 < e; p2++) {
                int cc = g_csrcol[S + p2];
                float w = g_weights[cc];
                uint2 hr = g_xh[(size_t)cc * 32 + lane];
                float2 f01 = __half22float2(*(__half2*)&hr.x);
                float2 f23 = __half22float2(*(__half2*)&hr.y);
                acc[t].x += f01.x * w; acc[t].y += f01.y * w;
                acc[t].z += f23.x * w; acc[t].w += f23.y * w;
            }
        }

        // ---- MLP1 (f32x2, shuffles)
        ull A[4], B[4], a0[4], a1[4];
        #pragma unroll
        for (int t = 0; t < 4; t++) {
            A[t] = pk2(acc[t].x, acc[t].y);
            B[t] = pk2(acc[t].z, acc[t].w);
            a0[t] = pk2(sb1[2 * lane], 0.f);
            a1[t] = pk2(sb1[2 * lane + 1], 0.f);
        }
        #pragma unroll 4
        for (int kk = 0; kk < 32; kk++) {
            ulonglong2 w0 = W1v[(2 * kk) * 32 + lane];
            ulonglong2 w1 = W1v[(2 * kk + 1) * 32 + lane];
            #pragma unroll
            for (int t = 0; t < 4; t++) {
                ull pa = __shfl_sync(FULL, A[t], kk);
                ull pb = __shfl_sync(FULL, B[t], kk);
                a0[t] = ffma2(pa, w0.x, a0[t]);
                a0[t] = ffma2(pb, w1.x, a0[t]);
                a1[t] = ffma2(pa, w0.y, a1[t]);
                a1[t] = ffma2(pb, w1.y, a1[t]);
            }
        }
        ull hp[4];
        #pragma unroll
        for (int t = 0; t < 4; t++) {
            float h0 = fmaxf(hsum2(a0[t]), 0.f);
            float h1 = fmaxf(hsum2(a1[t]), 0.f);
            hp[t] = pk2(h0, h1);
        }

        // ---- MLP2 (f32x2) + residual
        ull q0[4], q1[4], q2[4], q3[4];
        #pragma unroll
        for (int t = 0; t < 4; t++) {
            float4 bb = sb2[lane];
            q0[t] = pk2(bb.x, 0.f);
            q1[t] = pk2(bb.y, 0.f);
            q2[t] = pk2(bb.z, 0.f);
            q3[t] = pk2(bb.w, 0.f);
        }
        #pragma unroll 4
        for (int m = 0; m < 32; m++) {
            ulonglong2 wa = W2v[m * 64 + 2 * lane];
            ulonglong2 wb = W2v[m * 64 + 2 * lane + 1];
            #pragma unroll
            for (int t = 0; t < 4; t++) {
                ull u = __shfl_sync(FULL, hp[t], m);
                q0[t] = ffma2(u, wa.x, q0[t]);
                q1[t] = ffma2(u, wa.y, q1[t]);
                q2[t] = ffma2(u, wb.x, q2[t]);
                q3[t] = ffma2(u, wb.y, q3[t]);
            }
        }
        #pragma unroll
        for (int t = 0; t < 4; t++) {
            int n = n0 + t;
            if (n < N) {
                float4 xv = x4[(size_t)n * 32 + lane];
                out4[(size_t)n * 32 + lane] = make_float4(
                    xv.x + hsum2(q0[t]), xv.y + hsum2(q1[t]),
                    xv.z + hsum2(q2[t]), xv.w + hsum2(q3[t]));
            }
        }
    }
}

// ---------------- launch -------------------------------------------------------
extern "C" void kernel_launch(void* const* d_in, const int* in_sizes, int n_in,
                              void* d_out, int out_size) {
    const float* x    = (const float*)d_in[0];
    const void*  ei   = d_in[1];
    const float* Wsim = (const float*)d_in[2];
    const float* bsim = (const float*)d_in[3];
    const float* wvec = (const float*)d_in[4];
    const float* bvec = (const float*)d_in[5];
    const float* W1   = (const float*)d_in[6];
    const float* b1   = (const float*)d_in[7];
    const float* W2   = (const float*)d_in[8];
    const float* b2   = (const float*)d_in[9];
    float* out = (float*)d_out;

    int N = in_sizes[0] / D;
    int E = in_sizes[1] / 2;
    int nblk = (N + 1023) / 1024;
    int total4 = N * 32;

    int fused_smem = (16576 + 8 * 2 * CAP) * (int)sizeof(float);  // 76544 B

    static int inited = 0;
    static cudaStream_t s2;
    static cudaEvent_t evFork, evJoin;
    if (!inited) {
        cudaStreamCreateWithFlags(&s2, cudaStreamNonBlocking);
        cudaEventCreateWithFlags(&evFork, cudaEventDisableTiming);
        cudaEventCreateWithFlags(&evJoin, cudaEventDisableTiming);
        cudaFuncSetAttribute(k_fused, cudaFuncAttributeMaxDynamicSharedMemorySize, fused_smem);
        inited = 1;
    }

    // fork: side chain (fp16 convert + CSR build) runs concurrently with gate
    cudaEventRecord(evFork, 0);
    cudaStreamWaitEvent(s2, evFork, 0);

    k_gate<<<592, 256>>>((const float4*)x, Wsim, bsim, wvec, bvec, N);

    k_tohalf<<<(total4 + 255) / 256, 256, 0, s2>>>((const float4*)x, total4);
    k_detect<<<1, 32, 0, s2>>>(ei, E, N);
    k_zero<<<(N + 255) / 256, 256, 0, s2>>>(N);
    k_hist<<<2048, 256, 0, s2>>>(ei, E, N);
    k_scan1<<<nblk, 1024, 0, s2>>>(N);
    k_scan2<<<1, 128, 0, s2>>>(nblk, N, E);
    k_scan3<<<nblk, 1024, 0, s2>>>(N);
    k_fill<<<2048, 256, 0, s2>>>(ei, E, N);

    cudaEventRecord(evJoin, s2);
    cudaStreamWaitEvent(0, evJoin, 0);

    k_fused<<<444, 256, fused_smem>>>((const float4*)x, W1, b1, W2, b2, (float4*)out, N);
}

// round 11
// speedup vs baseline: 1.2211x; 1.2211x over previous
#include <cuda_runtime.h>

#define D 128
#define H 64
#define NMAX 100032
#define EMAX 1600000
#define FULL 0xffffffffu
#define CAP 160

typedef unsigned long long ull;

// ---------------- packed f32x2 helpers -----------------------------------------
__device__ __forceinline__ ull pk2(float lo, float hi) {
    ull r;
    asm("mov.b64 %0, {%1, %2};" : "=l"(r) : "f"(lo), "f"(hi));
    return r;
}
__device__ __forceinline__ void upk2(float& lo, float& hi, ull v) {
    asm("mov.b64 {%0, %1}, %2;" : "=f"(lo), "=f"(hi) : "l"(v));
}
__device__ __forceinline__ ull ffma2(ull a, ull b, ull c) {
    ull d;
    asm("fma.rn.f32x2 %0, %1, %2, %3;" : "=l"(d) : "l"(a), "l"(b), "l"(c));
    return d;
}
__device__ __forceinline__ float hsum2(ull v) {
    float lo, hi; upk2(lo, hi, v); return lo + hi;
}

// ---------------- scratch (static device globals; no allocations) -------------
__device__ float g_weights[NMAX];
__device__ int   g_deg[NMAX];
__device__ int   g_rowoff[NMAX + 1];
__device__ int   g_cursor[NMAX];
__device__ int   g_csrcol[EMAX];
__device__ int   g_partials[256];
__device__ int   g_is64;
__device__ ull   g_Y[(size_t)NMAX * 32];   // Y = x@W1, per node 64 floats as 32 packed pairs

// ---------------- dtype detection (1 warp) -------------------------------------
__global__ void k_detect(const void* __restrict__ ei, int E, int N) {
    const long long* e64 = (const long long*)ei;
    int lane = threadIdx.x;
    int ok = 1;
    if (lane < E) {
        long long v = e64[lane];
        ok = (v >= 0 && v < (long long)N) ? 1 : 0;
    }
    unsigned m = __ballot_sync(FULL, ok);
    if (lane == 0) g_is64 = (m == FULL) ? 1 : 0;
}

__device__ __forceinline__ int edge_at(const void* ei, size_t idx, int is64, int N) {
    long long v = is64 ? ((const long long*)ei)[idx] : (long long)((const int*)ei)[idx];
    if (v < 0) v = 0;
    if (v >= N) v = N - 1;
    return (int)v;
}

__global__ void k_zero(int N) {
    int i = blockIdx.x * blockDim.x + threadIdx.x;
    if (i < N) g_deg[i] = 0;
}

// ---------------- gate2: weights[n] = sigmoid(...)  AND  Y[n] = x[n]@W1 --------
// dyn smem floats: [0,8192) sWsim packed; [8192,16384) sW1 packed;
// sv=16384 (wvec, 64); sbs=16448 (bsim, 64). Total 16512 floats = 66048 B.
__global__ void k_gate2(const float4* __restrict__ x4, const float* __restrict__ Wsim,
                        const float* __restrict__ bsim, const float* __restrict__ wvec,
                        const float* __restrict__ bvec, const float* __restrict__ W1,
                        int N) {
    extern __shared__ float sm[];
    float4* sWs = (float4*)sm;
    float4* sW1 = (float4*)(sm + 8192);
    float*  sv  = sm + 16384;
    float*  sbs = sm + 16448;
    int tid = threadIdx.x;
    for (int i = tid; i < 64 * 32; i += blockDim.x) {
        int kp = i >> 5, l = i & 31;
        sWs[i] = make_float4(Wsim[(2 * kp) * H + 2 * l], Wsim[(2 * kp + 1) * H + 2 * l],
                             Wsim[(2 * kp) * H + 2 * l + 1], Wsim[(2 * kp + 1) * H + 2 * l + 1]);
        sW1[i] = make_float4(W1[(2 * kp) * H + 2 * l], W1[(2 * kp + 1) * H + 2 * l],
                             W1[(2 * kp) * H + 2 * l + 1], W1[(2 * kp + 1) * H + 2 * l + 1]);
    }
    if (tid < H) { sv[tid] = wvec[tid]; sbs[tid] = bsim[tid]; }
    __syncthreads();
    float bv = bvec[0];
    const ulonglong2* Wsv = (const ulonglong2*)sWs;
    const ulonglong2* W1v = (const ulonglong2*)sW1;

    int lane = tid & 31, wp = tid >> 5;
    int gw = blockIdx.x * (blockDim.x >> 5) + wp;
    int nw = gridDim.x * (blockDim.x >> 5);
    int ngroups = (N + 3) >> 2;
    for (int g = gw; g < ngroups; g += nw) {
        int n0 = g * 4;
        ull A[4], B[4], a0[4], a1[4], y0[4], y1[4];
        #pragma unroll
        for (int t = 0; t < 4; t++) {
            int n = n0 + t;
            float4 xv = (n < N) ? x4[(size_t)n * 32 + lane] : make_float4(0.f, 0.f, 0.f, 0.f);
            A[t] = pk2(xv.x, xv.y);
            B[t] = pk2(xv.z, xv.w);
            a0[t] = pk2(sbs[2 * lane], 0.f);
            a1[t] = pk2(sbs[2 * lane + 1], 0.f);
            y0[t] = 0; y1[t] = 0;
        }
        #pragma unroll 2
        for (int kk = 0; kk < 32; kk++) {
            ulonglong2 s0 = Wsv[(2 * kk) * 32 + lane];
            ulonglong2 s1 = Wsv[(2 * kk + 1) * 32 + lane];
            ulonglong2 u0 = W1v[(2 * kk) * 32 + lane];
            ulonglong2 u1 = W1v[(2 * kk + 1) * 32 + lane];
            #pragma unroll
            for (int t = 0; t < 4; t++) {
                ull pa = __shfl_sync(FULL, A[t], kk);
                ull pb = __shfl_sync(FULL, B[t], kk);
                a0[t] = ffma2(pa, s0.x, a0[t]);
                a0[t] = ffma2(pb, s1.x, a0[t]);
                a1[t] = ffma2(pa, s0.y, a1[t]);
                a1[t] = ffma2(pb, s1.y, a1[t]);
                y0[t] = ffma2(pa, u0.x, y0[t]);
                y0[t] = ffma2(pb, u1.x, y0[t]);
                y1[t] = ffma2(pa, u0.y, y1[t]);
                y1[t] = ffma2(pb, u1.y, y1[t]);
            }
        }
        #pragma unroll
        for (int t = 0; t < 4; t++) {
            int n = n0 + t;
            if (n < N)
                g_Y[(size_t)n * 32 + lane] = pk2(hsum2(y0[t]), hsum2(y1[t]));
            float h0 = tanhf(hsum2(a0[t]));
            float h1 = tanhf(hsum2(a1[t]));
            float s = h0 * sv[2 * lane] + h1 * sv[2 * lane + 1];
            #pragma unroll
            for (int o = 16; o > 0; o >>= 1) s += __shfl_xor_sync(FULL, s, o);
            if (lane == 0 && n < N)
                g_weights[n] = 1.f / (1.f + __expf(-(s + bv)));
        }
    }
}

// ---------------- CSR build ----------------------------------------------------
__global__ void k_hist(const void* __restrict__ ei, int E, int N) {
    int is64 = g_is64;
    int i = blockIdx.x * blockDim.x + threadIdx.x;
    int stride = gridDim.x * blockDim.x;
    for (; i < E; i += stride) atomicAdd(&g_deg[edge_at(ei, i, is64, N)], 1);
}

__global__ void k_scan1(int N) {
    int i = blockIdx.x * 1024 + threadIdx.x;
    int v = (i < N) ? g_deg[i] : 0;
    #pragma unroll
    for (int o = 16; o > 0; o >>= 1) v += __shfl_xor_sync(FULL, v, o);
    __shared__ int ws[32];
    int lane = threadIdx.x & 31, w = threadIdx.x >> 5;
    if (lane == 0) ws[w] = v;
    __syncthreads();
    if (w == 0) {
        int s = ws[lane];
        #pragma unroll
        for (int o = 16; o > 0; o >>= 1) s += __shfl_xor_sync(FULL, s, o);
        if (lane == 0) g_partials[blockIdx.x] = s;
    }
}

__global__ void k_scan2(int nblk, int N, int E) {
    __shared__ int s[128];
    int tid = threadIdx.x;
    int v = (tid < nblk) ? g_partials[tid] : 0;
    s[tid] = v;
    __syncthreads();
    for (int o = 1; o < 128; o <<= 1) {
        int t = 0;
        if (tid >= o) t = s[tid - o];
        __syncthreads();
        s[tid] += t;
        __syncthreads();
    }
    if (tid < nblk) g_partials[tid] = s[tid] - v;
    if (tid == 0) g_rowoff[N] = E;
}

__global__ void k_scan3(int N) {
    int i = blockIdx.x * 1024 + threadIdx.x;
    int lane = threadIdx.x & 31, w = threadIdx.x >> 5;
    int v = (i < N) ? g_deg[i] : 0;
    int s = v;
    #pragma unroll
    for (int o = 1; o < 32; o <<= 1) {
        int t = __shfl_up_sync(FULL, s, o);
        if (lane >= o) s += t;
    }
    __shared__ int ws[32];
    if (lane == 31) ws[w] = s;
    __syncthreads();
    if (w == 0) {
        int t2 = ws[lane];
        #pragma unroll
        for (int o = 1; o < 32; o <<= 1) {
            int u = __shfl_up_sync(FULL, t2, o);
            if (lane >= o) t2 += u;
        }
        ws[lane] = t2;
    }
    __syncthreads();
    int excl = s - v + ((w > 0) ? ws[w - 1] : 0) + g_partials[blockIdx.x];
    if (i < N) { g_rowoff[i] = excl; g_cursor[i] = excl; }
}

__global__ void k_fill(const void* __restrict__ ei, int E, int N) {
    int is64 = g_is64;
    int i = blockIdx.x * blockDim.x + threadIdx.x;
    int stride = gridDim.x * blockDim.x;
    for (; i < E; i += stride) {
        int r = edge_at(ei, i, is64, N);
        int c = edge_at(ei, (size_t)E + i, is64, N);
        int pos = atomicAdd(&g_cursor[r], 1);
        if (pos >= 0 && pos < EMAX) g_csrcol[pos] = c;
    }
}

// ---------------- FUSED2: gather Y (64-dim) + relu + MLP2 + residual -----------
// dyn smem floats: [0,8192) sW2p; sb1p=8192 (ull[32]=64 floats); sb2=8256 (32 float4=128);
// stage=8384: per warp 2*CAP floats. Total 8384 + 8*320 = 10944 floats = 43776 B.
__global__ void k_fused2(const float4* __restrict__ x4,
                         const float* __restrict__ b1,
                         const float* __restrict__ W2, const float* __restrict__ b2,
                         float4* __restrict__ out4, int N) {
    extern __shared__ float sm[];
    float2* sW2p = (float2*)sm;
    ull*    sb1p = (ull*)(sm + 8192);
    float4* sb2  = (float4*)(sm + 8256);

    int tid = threadIdx.x;
    for (int i = tid; i < 32 * D; i += blockDim.x) {
        int m = i >> 7, d = i & 127;
        sW2p[i] = make_float2(W2[(2 * m) * D + d], W2[(2 * m + 1) * D + d]);
    }
    if (tid < 32) {
        sb1p[tid] = pk2(b1[2 * tid], b1[2 * tid + 1]);
        sb2[tid] = ((const float4*)b2)[tid];
    }
    __syncthreads();

    const ulonglong2* W2v = (const ulonglong2*)sW2p;

    int lane = tid & 31, wp = tid >> 5;
    int*   scol = (int*)(sm + 8384) + wp * 2 * CAP;
    float* swt  = (float*)(scol + CAP);

    int gw = blockIdx.x * (blockDim.x >> 5) + wp;
    int nw = gridDim.x * (blockDim.x >> 5);
    int ngroups = (N + 3) >> 2;

    for (int g = gw; g < ngroups; g += nw) {
        int n0 = g * 4;
        int nlast = (n0 + 4 < N) ? n0 + 4 : N;

        // ---- cooperative stage of this group's contiguous CSR slab
        int S = g_rowoff[n0];
        int Eend = g_rowoff[nlast];
        int degT = Eend - S;
        int nst = (degT < CAP) ? degT : CAP;
        __syncwarp();
        for (int i = lane; i < nst; i += 32) {
            int c = g_csrcol[S + i];
            scol[i] = c;
            swt[i] = g_weights[c];
        }
        __syncwarp();

        // ---- gather Z[t] = b1 + sum w[col]*Y[col]  (packed dims 2l, 2l+1)
        ull Zp[4];
        #pragma unroll
        for (int t = 0; t < 4; t++) {
            Zp[t] = sb1p[lane];
            int n = n0 + t;
            if (n >= N) continue;
            int s = g_rowoff[n] - S;
            int e = g_rowoff[n + 1] - S;
            int elim = (e < nst) ? e : nst;
            int p = s;
            for (; p + 8 <= elim; p += 8) {
                int c[8]; float wv[8]; ull yv[8];
                #pragma unroll
                for (int q = 0; q < 8; q++) c[q] = scol[p + q];
                #pragma unroll
                for (int q = 0; q < 8; q++) wv[q] = swt[p + q];
                #pragma unroll
                for (int q = 0; q < 8; q++) yv[q] = g_Y[(size_t)c[q] * 32 + lane];
                #pragma unroll
                for (int q = 0; q < 8; q++)
                    Zp[t] = ffma2(yv[q], pk2(wv[q], wv[q]), Zp[t]);
            }
            for (; p < elim; p++) {
                float w = swt[p];
                ull yv = g_Y[(size_t)scol[p] * 32 + lane];
                Zp[t] = ffma2(yv, pk2(w, w), Zp[t]);
            }
            // overflow beyond staged CAP (essentially never)
            for (int p2 = (s > nst ? s : nst); p2 < e; p2++) {
                int cc = g_csrcol[S + p2];
                float w = g_weights[cc];
                ull yv = g_Y[(size_t)cc * 32 + lane];
                Zp[t] = ffma2(yv, pk2(w, w), Zp[t]);
            }
        }

        // ---- relu -> hidden pairs (h[2l], h[2l+1])
        ull hp[4];
        #pragma unroll
        for (int t = 0; t < 4; t++) {
            float lo, hi;
            upk2(lo, hi, Zp[t]);
            hp[t] = pk2(fmaxf(lo, 0.f), fmaxf(hi, 0.f));
        }

        // ---- MLP2 (f32x2) + residual
        ull q0[4], q1[4], q2[4], q3[4];
        #pragma unroll
        for (int t = 0; t < 4; t++) {
            float4 bb = sb2[lane];
            q0[t] = pk2(bb.x, 0.f);
            q1[t] = pk2(bb.y, 0.f);
            q2[t] = pk2(bb.z, 0.f);
            q3[t] = pk2(bb.w, 0.f);
        }
        #pragma unroll 4
        for (int m = 0; m < 32; m++) {
            ulonglong2 wa = W2v[m * 64 + 2 * lane];
            ulonglong2 wb = W2v[m * 64 + 2 * lane + 1];
            #pragma unroll
            for (int t = 0; t < 4; t++) {
                ull u = __shfl_sync(FULL, hp[t], m);
                q0[t] = ffma2(u, wa.x, q0[t]);
                q1[t] = ffma2(u, wa.y, q1[t]);
                q2[t] = ffma2(u, wb.x, q2[t]);
                q3[t] = ffma2(u, wb.y, q3[t]);
            }
        }
        #pragma unroll
        for (int t = 0; t < 4; t++) {
            int n = n0 + t;
            if (n < N) {
                float4 xv = x4[(size_t)n * 32 + lane];
                out4[(size_t)n * 32 + lane] = make_float4(
                    xv.x + hsum2(q0[t]), xv.y + hsum2(q1[t]),
                    xv.z + hsum2(q2[t]), xv.w + hsum2(q3[t]));
            }
        }
    }
}

// ---------------- launch -------------------------------------------------------
extern "C" void kernel_launch(void* const* d_in, const int* in_sizes, int n_in,
                              void* d_out, int out_size) {
    const float* x    = (const float*)d_in[0];
    const void*  ei   = d_in[1];
    const float* Wsim = (const float*)d_in[2];
    const float* bsim = (const float*)d_in[3];
    const float* wvec = (const float*)d_in[4];
    const float* bvec = (const float*)d_in[5];
    const float* W1   = (const float*)d_in[6];
    const float* b1   = (const float*)d_in[7];
    const float* W2   = (const float*)d_in[8];
    const float* b2   = (const float*)d_in[9];
    float* out = (float*)d_out;

    int N = in_sizes[0] / D;
    int E = in_sizes[1] / 2;
    int nblk = (N + 1023) / 1024;

    int gate_smem  = 16512 * (int)sizeof(float);                 // 66048 B
    int fused_smem = (8384 + 8 * 2 * CAP) * (int)sizeof(float);  // 43776 B -> 5 CTAs/SM

    static int inited = 0;
    static cudaStream_t s2;
    static cudaEvent_t evFork, evJoin;
    if (!inited) {
        cudaStreamCreateWithFlags(&s2, cudaStreamNonBlocking);
        cudaEventCreateWithFlags(&evFork, cudaEventDisableTiming);
        cudaEventCreateWithFlags(&evJoin, cudaEventDisableTiming);
        cudaFuncSetAttribute(k_gate2,  cudaFuncAttributeMaxDynamicSharedMemorySize, gate_smem);
        cudaFuncSetAttribute(k_fused2, cudaFuncAttributeMaxDynamicSharedMemorySize, fused_smem);
        inited = 1;
    }

    // fork: CSR build chain on s2 concurrently with gate+Y GEMMs on stream 0
    cudaEventRecord(evFork, 0);
    cudaStreamWaitEvent(s2, evFork, 0);

    k_gate2<<<592, 256, gate_smem>>>((const float4*)x, Wsim, bsim, wvec, bvec, W1, N);

    k_detect<<<1, 32, 0, s2>>>(ei, E, N);
    k_zero<<<(N + 255) / 256, 256, 0, s2>>>(N);
    k_hist<<<2048, 256, 0, s2>>>(ei, E, N);
    k_scan1<<<nblk, 1024, 0, s2>>>(N);
    k_scan2<<<1, 128, 0, s2>>>(nblk, N, E);
    k_scan3<<<nblk, 1024, 0, s2>>>(N);
    k_fill<<<2048, 256, 0, s2>>>(ei, E, N);

    cudaEventRecord(evJoin, s2);
    cudaStreamWaitEvent(0, evJoin, 0);

    k_fused2<<<740, 256, fused_smem>>>((const float4*)x, b1, W2, b2, (float4*)out, N);
}